// round 3
// baseline (speedup 1.0000x reference)
#include <cuda_runtime.h>
#include <cuda_bf16.h>

#define N_NODES 50000
#define N_EDGES 1600000
#define DIM 128

// ---------------- scratch (allocation-free) ----------------
__device__ int   g_row_off[N_NODES + 1];
__device__ float g_HW[(size_t)N_NODES * DIM];   // H @ W, 25.6 MB

// packed f32x2 FMA: d = a*b + d  (two fp32 lanes per instruction)
#define FFMA2(d, a, b) asm("fma.rn.f32x2 %0, %1, %2, %0;" : "+l"(d) : "l"(a), "l"(b))

__device__ __forceinline__ unsigned long long dup2(float v) {
    unsigned u = __float_as_uint(v);
    return (unsigned long long)u | ((unsigned long long)u << 32);
}
__device__ __forceinline__ float lo32(unsigned long long v) {
    return __uint_as_float((unsigned)v);
}
__device__ __forceinline__ float hi32(unsigned long long v) {
    return __uint_as_float((unsigned)(v >> 32));
}

// ---------------- Kernel A: CSR row offsets via binary search ----------------
__global__ void build_offsets_kernel(const int* __restrict__ dst) {
    int i = blockIdx.x * blockDim.x + threadIdx.x;
    if (i > N_NODES) return;
    int lo = 0, hi = N_EDGES;
    while (lo < hi) {
        int mid = (lo + hi) >> 1;
        if (dst[mid] < i) lo = mid + 1; else hi = mid;
    }
    g_row_off[i] = lo;
}

// ---------------- Kernel B: HW = H @ W  (f32x2 SGEMM, 32-row tiles) ----------------
// block: 256 threads, 8 warps; warp w owns rows w*4..w*4+3; lane owns cols lane*4..+3
__global__ __launch_bounds__(256, 4)
void gemm_kernel(const float* __restrict__ H, const float* __restrict__ W) {
    __shared__ unsigned long long sH2[32][DIM + 2];   // duplicated (h,h) pairs, ~33 KB

    const int tid  = threadIdx.x;
    const int wid  = tid >> 5;
    const int lane = tid & 31;
    const int base = blockIdx.x * 32;

    // stage H tile, duplicating each scalar into both f32x2 lanes
    const float4* __restrict__ H4 = (const float4*)H;
    #pragma unroll
    for (int j = tid; j < 32 * 32; j += 256) {          // 1024 float4 slots
        int row = j >> 5;
        int c4  = j & 31;
        int gr  = base + row;
        if (gr >= N_NODES) gr = N_NODES - 1;
        float4 h = H4[(size_t)gr * 32 + c4];
        int kq = c4 << 2;
        sH2[row][kq + 0] = dup2(h.x);
        sH2[row][kq + 1] = dup2(h.y);
        sH2[row][kq + 2] = dup2(h.z);
        sH2[row][kq + 3] = dup2(h.w);
    }
    __syncthreads();

    const unsigned long long* __restrict__ Wp = (const unsigned long long*)W;

    unsigned long long c[4][2];
    #pragma unroll
    for (int i = 0; i < 4; i++) { c[i][0] = 0ull; c[i][1] = 0ull; }

    #pragma unroll 4
    for (int k = 0; k < DIM; k += 4) {
        // W rows k..k+3, this lane's 4 columns as 2 packed pairs each (LDG.128 x4, L1-hot)
        const unsigned long long b00 = Wp[(size_t)(k + 0) * 64 + lane * 2];
        const unsigned long long b01 = Wp[(size_t)(k + 0) * 64 + lane * 2 + 1];
        const unsigned long long b10 = Wp[(size_t)(k + 1) * 64 + lane * 2];
        const unsigned long long b11 = Wp[(size_t)(k + 1) * 64 + lane * 2 + 1];
        const unsigned long long b20 = Wp[(size_t)(k + 2) * 64 + lane * 2];
        const unsigned long long b21 = Wp[(size_t)(k + 2) * 64 + lane * 2 + 1];
        const unsigned long long b30 = Wp[(size_t)(k + 3) * 64 + lane * 2];
        const unsigned long long b31 = Wp[(size_t)(k + 3) * 64 + lane * 2 + 1];
        #pragma unroll
        for (int i = 0; i < 4; i++) {
            const int r = wid * 4 + i;
            ulonglong2 A = *(const ulonglong2*)&sH2[r][k];       // dup(a_k), dup(a_k+1)
            ulonglong2 B = *(const ulonglong2*)&sH2[r][k + 2];   // dup(a_k+2), dup(a_k+3)
            FFMA2(c[i][0], A.x, b00); FFMA2(c[i][1], A.x, b01);
            FFMA2(c[i][0], A.y, b10); FFMA2(c[i][1], A.y, b11);
            FFMA2(c[i][0], B.x, b20); FFMA2(c[i][1], B.x, b21);
            FFMA2(c[i][0], B.y, b30); FFMA2(c[i][1], B.y, b31);
        }
    }

    float4* __restrict__ HWo = (float4*)g_HW;
    #pragma unroll
    for (int i = 0; i < 4; i++) {
        int row = base + wid * 4 + i;
        if (row < N_NODES) {
            float4 o;
            o.x = lo32(c[i][0]); o.y = hi32(c[i][0]);
            o.z = lo32(c[i][1]); o.w = hi32(c[i][1]);
            HWo[(size_t)row * 32 + lane] = o;
        }
    }
}

// ---------------- Kernel C: out[n] = b + sum_e w_e * HW[src_e]  ----------------
// warp-per-node, no smem, 8-deep gather batching
__global__ __launch_bounds__(256, 4)
void gather_kernel(const int* __restrict__ esrc,
                   const float* __restrict__ ew,
                   const float* __restrict__ bias,
                   float* __restrict__ out)
{
    const int lane = threadIdx.x & 31;
    const int node = (blockIdx.x * 256 + threadIdx.x) >> 5;
    if (node >= N_NODES) return;

    const int s = g_row_off[node];
    const int e = g_row_off[node + 1];

    const float4* __restrict__ HW4 = (const float4*)g_HW;

    float4 acc = make_float4(0.f, 0.f, 0.f, 0.f);

    int q = s;
    #pragma unroll 1
    for (; q + 8 <= e; q += 8) {
        int   ss[8];
        float ww[8];
        #pragma unroll
        for (int i = 0; i < 8; i++) { ss[i] = esrc[q + i]; ww[i] = ew[q + i]; }
        float4 hh[8];
        #pragma unroll
        for (int i = 0; i < 8; i++) hh[i] = HW4[(size_t)ss[i] * 32 + lane];
        #pragma unroll
        for (int i = 0; i < 8; i++) {
            acc.x += ww[i] * hh[i].x;
            acc.y += ww[i] * hh[i].y;
            acc.z += ww[i] * hh[i].z;
            acc.w += ww[i] * hh[i].w;
        }
    }
    #pragma unroll 1
    for (; q < e; ++q) {
        const int   si = esrc[q];
        const float wi = ew[q];
        const float4 h = HW4[(size_t)si * 32 + lane];
        acc.x += wi * h.x; acc.y += wi * h.y;
        acc.z += wi * h.z; acc.w += wi * h.w;
    }

    const float4 bb = ((const float4*)bias)[lane];
    float4 o;
    o.x = acc.x + bb.x; o.y = acc.y + bb.y;
    o.z = acc.z + bb.z; o.w = acc.w + bb.w;
    ((float4*)out)[(size_t)node * 32 + lane] = o;
}

extern "C" void kernel_launch(void* const* d_in, const int* in_sizes, int n_in,
                              void* d_out, int out_size) {
    const float* H    = (const float*)d_in[0];
    const int*   esrc = (const int*)  d_in[1];
    const int*   edst = (const int*)  d_in[2];
    const float* ew   = (const float*)d_in[3];
    const float* W    = (const float*)d_in[4];
    const float* b    = (const float*)d_in[5];
    float* out = (float*)d_out;

    build_offsets_kernel<<<(N_NODES + 1 + 255) / 256, 256>>>(edst);

    gemm_kernel<<<(N_NODES + 31) / 32, 256>>>(H, W);

    const int nwarps  = N_NODES;                 // one warp per node
    const int nblocks = (nwarps * 32 + 255) / 256;
    gather_kernel<<<nblocks, 256>>>(esrc, ew, b, out);
}

// round 4
// speedup vs baseline: 1.6320x; 1.6320x over previous
#include <cuda_runtime.h>
#include <cuda_bf16.h>

#define N_NODES 50000
#define N_EDGES 1600000
#define DIM 128
#define NODES_PER_BLOCK 64
#define THREADS 256

// CSR row offsets scratch (allocation-free: __device__ global)
__device__ int g_row_off[N_NODES + 1];

// ---------------- Kernel A: offsets via coalesced boundary scan ----------------
// row_off[n] = first edge index i with dst[i] >= n.
__global__ void scan_offsets_kernel(const int* __restrict__ dst) {
    int i = blockIdx.x * blockDim.x + threadIdx.x;
    if (i >= N_EDGES) return;
    const int d = dst[i];
    const int prev = (i == 0) ? -1 : dst[i - 1];
    for (int j = prev + 1; j <= d; j++) g_row_off[j] = i;
    if (i == N_EDGES - 1) {
        for (int j = d + 1; j <= N_NODES; j++) g_row_off[j] = N_EDGES;
    }
}

// ---------------- Kernel B: fused aggregate + 64x128 SGEMM epilogue ----------------
__global__ __launch_bounds__(THREADS, 4)
void gcn_fused_kernel(const float* __restrict__ H,
                      const int* __restrict__ esrc,
                      const float* __restrict__ ew,
                      const float* __restrict__ W,
                      const float* __restrict__ bias,
                      float* __restrict__ out)
{
    __shared__ float sAgg[NODES_PER_BLOCK][DIM];   // 32 KB (only smem user)

    const int tid  = threadIdx.x;
    const int wid  = tid >> 5;
    const int lane = tid & 31;
    const int base = blockIdx.x * NODES_PER_BLOCK;

    const float4* __restrict__ H4 = (const float4*)H;

    // -------- Aggregation: each warp handles 8 consecutive nodes, 8-deep gathers --------
    #pragma unroll 1
    for (int r = 0; r < NODES_PER_BLOCK / 8; r++) {
        const int rowLocal = wid * 8 + r;
        const int node = base + rowLocal;
        float4 acc = make_float4(0.f, 0.f, 0.f, 0.f);

        if (node < N_NODES) {
            const int s = g_row_off[node];
            const int e = g_row_off[node + 1];
            #pragma unroll 1
            for (int p = s; p < e; p += 32) {
                const int idx = p + lane;
                int   src = 0;
                float w   = 0.f;
                if (idx < e) { src = esrc[idx]; w = ew[idx]; }
                const int cnt = min(32, e - p);
                if (cnt == 32) {
                    #pragma unroll
                    for (int g = 0; g < 32; g += 8) {
                        int   ss[8];
                        float ws[8];
                        #pragma unroll
                        for (int i = 0; i < 8; i++) {
                            ss[i] = __shfl_sync(0xffffffffu, src, g + i);
                            ws[i] = __shfl_sync(0xffffffffu, w,   g + i);
                        }
                        float4 hh[8];
                        #pragma unroll
                        for (int i = 0; i < 8; i++)
                            hh[i] = H4[(size_t)ss[i] * 32 + lane];
                        #pragma unroll
                        for (int i = 0; i < 8; i++) {
                            acc.x += ws[i] * hh[i].x;
                            acc.y += ws[i] * hh[i].y;
                            acc.z += ws[i] * hh[i].z;
                            acc.w += ws[i] * hh[i].w;
                        }
                    }
                } else {
                    for (int i = 0; i < cnt; i++) {
                        const int   ss = __shfl_sync(0xffffffffu, src, i);
                        const float sw = __shfl_sync(0xffffffffu, w,   i);
                        const float4 h = H4[(size_t)ss * 32 + lane];
                        acc.x += sw * h.x; acc.y += sw * h.y;
                        acc.z += sw * h.z; acc.w += sw * h.w;
                    }
                }
            }
        }
        ((float4*)sAgg[rowLocal])[lane] = acc;
    }

    __syncthreads();

    // -------- GEMM epilogue: C[64x128] = sAgg @ W + b, W streamed from L1 --------
    // warp ty owns rows ty*8..ty*8+7; lane tx owns cols 4tx..4tx+3
    const int tx = lane;
    const int ty = wid;
    float c[8][4];
    #pragma unroll
    for (int i = 0; i < 8; i++)
        #pragma unroll
        for (int j = 0; j < 4; j++) c[i][j] = 0.f;

    const float4* __restrict__ W4 = (const float4*)W;   // row k, cols 4tx..4tx+3 at W4[k*32+tx]

    #pragma unroll 2
    for (int k = 0; k < DIM; k += 2) {
        const float4 b0 = W4[(size_t)(k + 0) * 32 + tx];
        const float4 b1 = W4[(size_t)(k + 1) * 32 + tx];
        #pragma unroll
        for (int i = 0; i < 8; i++) {
            const float2 a = *(const float2*)&sAgg[ty * 8 + i][k];  // warp-uniform broadcast
            c[i][0] += a.x * b0.x; c[i][1] += a.x * b0.y;
            c[i][2] += a.x * b0.z; c[i][3] += a.x * b0.w;
            c[i][0] += a.y * b1.x; c[i][1] += a.y * b1.y;
            c[i][2] += a.y * b1.z; c[i][3] += a.y * b1.w;
        }
    }

    const float4 bb = ((const float4*)bias)[tx];
    #pragma unroll
    for (int i = 0; i < 8; i++) {
        const int row = base + ty * 8 + i;
        if (row < N_NODES) {
            float4 o;
            o.x = c[i][0] + bb.x;
            o.y = c[i][1] + bb.y;
            o.z = c[i][2] + bb.z;
            o.w = c[i][3] + bb.w;
            ((float4*)(out + (size_t)row * DIM))[tx] = o;
        }
    }
}

extern "C" void kernel_launch(void* const* d_in, const int* in_sizes, int n_in,
                              void* d_out, int out_size) {
    const float* H    = (const float*)d_in[0];
    const int*   esrc = (const int*)  d_in[1];
    const int*   edst = (const int*)  d_in[2];
    const float* ew   = (const float*)d_in[3];
    const float* W    = (const float*)d_in[4];
    const float* b    = (const float*)d_in[5];
    float* out = (float*)d_out;

    scan_offsets_kernel<<<(N_EDGES + 255) / 256, 256>>>(edst);

    const int nblocks = (N_NODES + NODES_PER_BLOCK - 1) / NODES_PER_BLOCK;
    gcn_fused_kernel<<<nblocks, THREADS>>>(H, esrc, ew, W, b, out);
}

// round 5
// speedup vs baseline: 1.8866x; 1.1560x over previous
#include <cuda_runtime.h>
#include <cuda_bf16.h>

#define N_NODES 50000
#define N_EDGES 1600000
#define DIM 128
#define NODES_PER_BLOCK 64
#define THREADS 256

// CSR row offsets scratch (allocation-free: __device__ global)
__device__ int g_row_off[N_NODES + 1];

// packed f32x2 FMA: d += a*b (two fp32 lanes per instruction)
#define FFMA2(d, a, b) asm("fma.rn.f32x2 %0, %1, %2, %0;" : "+l"(d) : "l"(a), "l"(b))

__device__ __forceinline__ unsigned long long dup2(float v) {
    unsigned long long d;
    unsigned u = __float_as_uint(v);
    asm("mov.b64 %0, {%1, %1};" : "=l"(d) : "r"(u));
    return d;
}
__device__ __forceinline__ float lo32(unsigned long long v) {
    return __uint_as_float((unsigned)v);
}
__device__ __forceinline__ float hi32(unsigned long long v) {
    return __uint_as_float((unsigned)(v >> 32));
}

// ---------------- Kernel A: offsets via coalesced boundary scan ----------------
__global__ void scan_offsets_kernel(const int* __restrict__ dst) {
    int i = blockIdx.x * blockDim.x + threadIdx.x;
    if (i >= N_EDGES) return;
    const int d = dst[i];
    const int prev = (i == 0) ? -1 : dst[i - 1];
    for (int j = prev + 1; j <= d; j++) g_row_off[j] = i;
    if (i == N_EDGES - 1) {
        for (int j = d + 1; j <= N_NODES; j++) g_row_off[j] = N_EDGES;
    }
}

// ---------------- Kernel B: fused aggregate + f32x2 SGEMM epilogue ----------------
__global__ __launch_bounds__(THREADS, 3)
void gcn_fused_kernel(const float* __restrict__ H,
                      const int* __restrict__ esrc,
                      const float* __restrict__ ew,
                      const float* __restrict__ W,
                      const float* __restrict__ bias,
                      float* __restrict__ out)
{
    // aggregate, stored duplicated: sAgg2[row][k] = (a, a) packed f32x2. 64 KB.
    __shared__ unsigned long long sAgg2[NODES_PER_BLOCK][DIM];

    const int tid  = threadIdx.x;
    const int wid  = tid >> 5;
    const int lane = tid & 31;
    const int base = blockIdx.x * NODES_PER_BLOCK;

    const float4* __restrict__ H4 = (const float4*)H;

    // -------- Aggregation: each warp handles 8 consecutive nodes, 4-deep gathers --------
    #pragma unroll 1
    for (int r = 0; r < NODES_PER_BLOCK / 8; r++) {
        const int rowLocal = wid * 8 + r;
        const int node = base + rowLocal;
        unsigned long long acc0 = 0ull, acc1 = 0ull;   // cols (4l,4l+1),(4l+2,4l+3)

        if (node < N_NODES) {
            const int s = g_row_off[node];
            const int e = g_row_off[node + 1];
            #pragma unroll 1
            for (int p = s; p < e; p += 32) {
                const int idx = p + lane;
                int   src = 0;
                float w   = 0.f;
                if (idx < e) { src = esrc[idx]; w = ew[idx]; }
                const int cnt = min(32, e - p);
                if (cnt == 32) {
                    #pragma unroll
                    for (int g = 0; g < 32; g += 4) {
                        int   ss[4];
                        float ws[4];
                        #pragma unroll
                        for (int i = 0; i < 4; i++) {
                            ss[i] = __shfl_sync(0xffffffffu, src, g + i);
                            ws[i] = __shfl_sync(0xffffffffu, w,   g + i);
                        }
                        float4 hh[4];
                        #pragma unroll
                        for (int i = 0; i < 4; i++)
                            hh[i] = H4[(size_t)ss[i] * 32 + lane];
                        #pragma unroll
                        for (int i = 0; i < 4; i++) {
                            const unsigned long long wd = dup2(ws[i]);
                            ulonglong2 hp = *(const ulonglong2*)&hh[i];
                            FFMA2(acc0, wd, hp.x);
                            FFMA2(acc1, wd, hp.y);
                        }
                    }
                } else {
                    for (int i = 0; i < cnt; i++) {
                        const int   ss = __shfl_sync(0xffffffffu, src, i);
                        const float sw = __shfl_sync(0xffffffffu, w,   i);
                        const float4 h = H4[(size_t)ss * 32 + lane];
                        const unsigned long long wd = dup2(sw);
                        ulonglong2 hp = *(const ulonglong2*)&h;
                        FFMA2(acc0, wd, hp.x);
                        FFMA2(acc1, wd, hp.y);
                    }
                }
            }
        }
        // unpack + duplicate each scalar, store 4 dup'd values (32 B per lane)
        ulonglong2 d0, d1;
        d0.x = dup2(lo32(acc0)); d0.y = dup2(hi32(acc0));
        d1.x = dup2(lo32(acc1)); d1.y = dup2(hi32(acc1));
        *(ulonglong2*)&sAgg2[rowLocal][4 * lane]     = d0;
        *(ulonglong2*)&sAgg2[rowLocal][4 * lane + 2] = d1;
    }

    __syncthreads();

    // -------- f32x2 GEMM epilogue: C[64x128] = Agg @ W + b --------
    // warp ty owns rows ty*8..ty*8+7; lane tx owns cols 4tx..4tx+3 (2 packed pairs)
    const int tx = lane;
    const int ty = wid;
    unsigned long long c[8][2];
    #pragma unroll
    for (int i = 0; i < 8; i++) { c[i][0] = 0ull; c[i][1] = 0ull; }

    const unsigned long long* __restrict__ Wp = (const unsigned long long*)W;

    #pragma unroll 4
    for (int k = 0; k < DIM; k += 2) {
        // W rows k, k+1, this lane's 4 cols as 2 packed pairs each (L1-resident)
        const ulonglong2 w0 = *(const ulonglong2*)(Wp + (size_t)(k + 0) * 64 + tx * 2);
        const ulonglong2 w1 = *(const ulonglong2*)(Wp + (size_t)(k + 1) * 64 + tx * 2);
        #pragma unroll
        for (int i = 0; i < 8; i++) {
            const int r = ty * 8 + i;
            // dup(a_k), dup(a_k+1): one broadcast LDS.128
            const ulonglong2 A = *(const ulonglong2*)&sAgg2[r][k];
            FFMA2(c[i][0], A.x, w0.x); FFMA2(c[i][1], A.x, w0.y);
            FFMA2(c[i][0], A.y, w1.x); FFMA2(c[i][1], A.y, w1.y);
        }
    }

    const float4 bb = ((const float4*)bias)[tx];
    #pragma unroll
    for (int i = 0; i < 8; i++) {
        const int row = base + ty * 8 + i;
        if (row < N_NODES) {
            float4 o;
            o.x = lo32(c[i][0]) + bb.x;
            o.y = hi32(c[i][0]) + bb.y;
            o.z = lo32(c[i][1]) + bb.z;
            o.w = hi32(c[i][1]) + bb.w;
            ((float4*)(out + (size_t)row * DIM))[tx] = o;
        }
    }
}

extern "C" void kernel_launch(void* const* d_in, const int* in_sizes, int n_in,
                              void* d_out, int out_size) {
    const float* H    = (const float*)d_in[0];
    const int*   esrc = (const int*)  d_in[1];
    const int*   edst = (const int*)  d_in[2];
    const float* ew   = (const float*)d_in[3];
    const float* W    = (const float*)d_in[4];
    const float* b    = (const float*)d_in[5];
    float* out = (float*)d_out;

    scan_offsets_kernel<<<(N_EDGES + 255) / 256, 256>>>(edst);

    const int nblocks = (N_NODES + NODES_PER_BLOCK - 1) / NODES_PER_BLOCK;
    gcn_fused_kernel<<<nblocks, THREADS>>>(H, esrc, ew, W, b, out);
}

// round 6
// speedup vs baseline: 1.8989x; 1.0065x over previous
#include <cuda_runtime.h>
#include <cuda_bf16.h>

#define N_NODES 50000
#define N_EDGES 1600000
#define DIM 128
#define NODES_PER_BLOCK 64
#define THREADS 256

// CSR row offsets scratch (allocation-free: __device__ global)
__device__ int g_row_off[N_NODES + 1];

// packed f32x2 FMA: d += a*b (two fp32 lanes per instruction)
#define FFMA2(d, a, b) asm("fma.rn.f32x2 %0, %1, %2, %0;" : "+l"(d) : "l"(a), "l"(b))

__device__ __forceinline__ unsigned long long dup2(float v) {
    unsigned long long d;
    unsigned u = __float_as_uint(v);
    asm("mov.b64 %0, {%1, %1};" : "=l"(d) : "r"(u));
    return d;
}
__device__ __forceinline__ float lo32(unsigned long long v) {
    return __uint_as_float((unsigned)v);
}
__device__ __forceinline__ float hi32(unsigned long long v) {
    return __uint_as_float((unsigned)(v >> 32));
}

// ---------------- Kernel A: offsets via coalesced boundary scan ----------------
__global__ void scan_offsets_kernel(const int* __restrict__ dst) {
    int i = blockIdx.x * blockDim.x + threadIdx.x;
    if (i >= N_EDGES) return;
    const int d = dst[i];
    const int prev = (i == 0) ? -1 : dst[i - 1];
    for (int j = prev + 1; j <= d; j++) g_row_off[j] = i;
    if (i == N_EDGES - 1) {
        for (int j = d + 1; j <= N_NODES; j++) g_row_off[j] = N_EDGES;
    }
}

// ---------------- Kernel B: fused aggregate + f32x2 SGEMM epilogue ----------------
__global__ __launch_bounds__(THREADS, 3)
void gcn_fused_kernel(const float* __restrict__ H,
                      const int* __restrict__ esrc,
                      const float* __restrict__ ew,
                      const float* __restrict__ W,
                      const float* __restrict__ bias,
                      float* __restrict__ out)
{
    // aggregate, stored duplicated: sAgg2[row][k] = (a, a) packed f32x2. 64 KB.
    __shared__ unsigned long long sAgg2[NODES_PER_BLOCK][DIM];

    const int tid  = threadIdx.x;
    const int wid  = tid >> 5;
    const int lane = tid & 31;
    const int base = blockIdx.x * NODES_PER_BLOCK;

    const float4* __restrict__ H4 = (const float4*)H;

    // -------- Aggregation: each warp handles 8 consecutive nodes, 4-deep gathers --------
    #pragma unroll 1
    for (int r = 0; r < NODES_PER_BLOCK / 8; r++) {
        const int rowLocal = wid * 8 + r;
        const int node = base + rowLocal;
        unsigned long long acc0 = 0ull, acc1 = 0ull;   // cols (4l,4l+1),(4l+2,4l+3)

        if (node < N_NODES) {
            const int s = g_row_off[node];
            const int e = g_row_off[node + 1];
            #pragma unroll 1
            for (int p = s; p < e; p += 32) {
                const int idx = p + lane;
                int   src = 0;
                float w   = 0.f;     // zero-pad: lanes past end contribute nothing
                if (idx < e) { src = esrc[idx]; w = ew[idx]; }
                const int cnt = min(32, e - p);
                if (cnt == 32) {
                    // fast path: fully unrolled 8 groups of 4
                    #pragma unroll
                    for (int g = 0; g < 32; g += 4) {
                        int   ss[4];
                        float ws[4];
                        #pragma unroll
                        for (int i = 0; i < 4; i++) {
                            ss[i] = __shfl_sync(0xffffffffu, src, g + i);
                            ws[i] = __shfl_sync(0xffffffffu, w,   g + i);
                        }
                        float4 hh[4];
                        #pragma unroll
                        for (int i = 0; i < 4; i++)
                            hh[i] = H4[(size_t)ss[i] * 32 + lane];
                        #pragma unroll
                        for (int i = 0; i < 4; i++) {
                            const unsigned long long wd = dup2(ws[i]);
                            ulonglong2 hp = *(const ulonglong2*)&hh[i];
                            FFMA2(acc0, wd, hp.x);
                            FFMA2(acc1, wd, hp.y);
                        }
                    }
                } else {
                    // partial strip: SAME 4-deep batched structure, zero-padded.
                    // Padded broadcast lanes have w=0, src=0 -> gather H[0] (L1-hot), add 0.
                    #pragma unroll 1
                    for (int g = 0; g < cnt; g += 4) {
                        int   ss[4];
                        float ws[4];
                        #pragma unroll
                        for (int i = 0; i < 4; i++) {
                            ss[i] = __shfl_sync(0xffffffffu, src, g + i);
                            ws[i] = __shfl_sync(0xffffffffu, w,   g + i);
                        }
                        float4 hh[4];
                        #pragma unroll
                        for (int i = 0; i < 4; i++)
                            hh[i] = H4[(size_t)ss[i] * 32 + lane];
                        #pragma unroll
                        for (int i = 0; i < 4; i++) {
                            const unsigned long long wd = dup2(ws[i]);
                            ulonglong2 hp = *(const ulonglong2*)&hh[i];
                            FFMA2(acc0, wd, hp.x);
                            FFMA2(acc1, wd, hp.y);
                        }
                    }
                }
            }
        }
        // unpack + duplicate each scalar, store 4 dup'd values (32 B per lane)
        ulonglong2 d0, d1;
        d0.x = dup2(lo32(acc0)); d0.y = dup2(hi32(acc0));
        d1.x = dup2(lo32(acc1)); d1.y = dup2(hi32(acc1));
        *(ulonglong2*)&sAgg2[rowLocal][4 * lane]     = d0;
        *(ulonglong2*)&sAgg2[rowLocal][4 * lane + 2] = d1;
    }

    __syncthreads();

    // -------- f32x2 GEMM epilogue: C[64x128] = Agg @ W + b --------
    // warp ty owns rows ty*8..ty*8+7; lane tx owns cols 4tx..4tx+3 (2 packed pairs)
    const int tx = lane;
    const int ty = wid;
    unsigned long long c[8][2];
    #pragma unroll
    for (int i = 0; i < 8; i++) { c[i][0] = 0ull; c[i][1] = 0ull; }

    const unsigned long long* __restrict__ Wp = (const unsigned long long*)W;

    #pragma unroll 4
    for (int k = 0; k < DIM; k += 2) {
        // W rows k, k+1, this lane's 4 cols as 2 packed pairs each (L1-resident)
        const ulonglong2 w0 = *(const ulonglong2*)(Wp + (size_t)(k + 0) * 64 + tx * 2);
        const ulonglong2 w1 = *(const ulonglong2*)(Wp + (size_t)(k + 1) * 64 + tx * 2);
        #pragma unroll
        for (int i = 0; i < 8; i++) {
            const int r = ty * 8 + i;
            // dup(a_k), dup(a_k+1): one broadcast LDS.128
            const ulonglong2 A = *(const ulonglong2*)&sAgg2[r][k];
            FFMA2(c[i][0], A.x, w0.x); FFMA2(c[i][1], A.x, w0.y);
            FFMA2(c[i][0], A.y, w1.x); FFMA2(c[i][1], A.y, w1.y);
        }
    }

    const float4 bb = ((const float4*)bias)[tx];
    #pragma unroll
    for (int i = 0; i < 8; i++) {
        const int row = base + ty * 8 + i;
        if (row < N_NODES) {
            float4 o;
            o.x = lo32(c[i][0]) + bb.x;
            o.y = hi32(c[i][0]) + bb.y;
            o.z = lo32(c[i][1]) + bb.z;
            o.w = hi32(c[i][1]) + bb.w;
            ((float4*)(out + (size_t)row * DIM))[tx] = o;
        }
    }
}

extern "C" void kernel_launch(void* const* d_in, const int* in_sizes, int n_in,
                              void* d_out, int out_size) {
    const float* H    = (const float*)d_in[0];
    const int*   esrc = (const int*)  d_in[1];
    const int*   edst = (const int*)  d_in[2];
    const float* ew   = (const float*)d_in[3];
    const float* W    = (const float*)d_in[4];
    const float* b    = (const float*)d_in[5];
    float* out = (float*)d_out;

    scan_offsets_kernel<<<(N_EDGES + 255) / 256, 256>>>(edst);

    const int nblocks = (N_NODES + NODES_PER_BLOCK - 1) / NODES_PER_BLOCK;
    gcn_fused_kernel<<<nblocks, THREADS>>>(H, esrc, ew, W, b, out);
}